// round 3
// baseline (speedup 1.0000x reference)
#include <cuda_runtime.h>
#include <cstdint>

#define HID 128
#define NMAX 100000
#define CAP 64

// scratch (no cudaMalloc allowed): h for S,I rows (2n x 128), CSR adjacency
static __device__ float g_h[(size_t)2 * NMAX * HID];     // 102.4 MB
static __device__ int   g_cnt[NMAX];
static __device__ int   g_csr[(size_t)NMAX * CAP];       // 25.6 MB

__global__ void k_zero(int n) {
    int i = blockIdx.x * blockDim.x + threadIdx.x;
    if (i < n) g_cnt[i] = 0;
}

__global__ void k_fill(const int* __restrict__ er,
                       const int* __restrict__ ec, int E, int n) {
    int e = blockIdx.x * blockDim.x + threadIdx.x;
    if (e < E) {
        int r = er[e];
        int c = ec[e];
        if ((unsigned)r < (unsigned)n && (unsigned)c < (unsigned)n) {
            int pos = atomicAdd(&g_cnt[r], 1) & (CAP - 1);
            g_csr[(size_t)r * CAP + pos] = c;
        }
    }
}

__device__ __forceinline__ float to_tf32(float x) {
    unsigned u;
    asm("cvt.rna.tf32.f32 %0, %1;" : "=r"(u) : "f"(x));
    return __uint_as_float(u);
}

// H[r][c] = relu(sum_k A[r][k] * W[c][k] + b[c]), r < M. tf32 mma.sync.
// CTA: 256 threads, tile 128 rows x 128 cols; warp w owns rows [16w,16w+16).
__global__ void k_gemm(const float* __restrict__ A, const float* __restrict__ W,
                       const float* __restrict__ bias, int M) {
    extern __shared__ float sm[];
    float* As = sm;             // 128 x 132 (pad 4 -> conflict-free frag loads)
    float* Ws = sm + 128 * 132; // 128 x 132
    int tid = threadIdx.x;
    int row0 = blockIdx.x * 128;

    for (int i = tid; i < 128 * 32; i += 256) {
        int r = i >> 5, q = i & 31;
        float4 v = *(const float4*)(W + r * HID + q * 4);
        *(float4*)(Ws + r * 132 + q * 4) =
            make_float4(to_tf32(v.x), to_tf32(v.y), to_tf32(v.z), to_tf32(v.w));
    }
    for (int i = tid; i < 128 * 32; i += 256) {
        int r = i >> 5, q = i & 31;
        int gr = row0 + r;
        float4 v = make_float4(0.f, 0.f, 0.f, 0.f);
        if (gr < M) v = *(const float4*)(A + (size_t)gr * HID + q * 4);
        *(float4*)(As + r * 132 + q * 4) =
            make_float4(to_tf32(v.x), to_tf32(v.y), to_tf32(v.z), to_tf32(v.w));
    }
    __syncthreads();

    int w = tid >> 5, lane = tid & 31;
    int gid = lane >> 2, tig = lane & 3;

    float acc[16][4];
#pragma unroll
    for (int nt = 0; nt < 16; nt++)
        acc[nt][0] = acc[nt][1] = acc[nt][2] = acc[nt][3] = 0.f;

    const float* Ar = As + (w * 16 + gid) * 132;
#pragma unroll
    for (int k0 = 0; k0 < 128; k0 += 8) {
        unsigned a0 = __float_as_uint(Ar[k0 + tig]);
        unsigned a1 = __float_as_uint(Ar[8 * 132 + k0 + tig]);
        unsigned a2 = __float_as_uint(Ar[k0 + tig + 4]);
        unsigned a3 = __float_as_uint(Ar[8 * 132 + k0 + tig + 4]);
#pragma unroll
        for (int nt = 0; nt < 16; nt++) {
            unsigned b0 = __float_as_uint(Ws[(nt * 8 + gid) * 132 + k0 + tig]);
            unsigned b1 = __float_as_uint(Ws[(nt * 8 + gid) * 132 + k0 + tig + 4]);
            asm volatile(
                "mma.sync.aligned.m16n8k8.row.col.f32.tf32.tf32.f32 "
                "{%0,%1,%2,%3}, {%4,%5,%6,%7}, {%8,%9}, {%0,%1,%2,%3};"
                : "+f"(acc[nt][0]), "+f"(acc[nt][1]), "+f"(acc[nt][2]), "+f"(acc[nt][3])
                : "r"(a0), "r"(a1), "r"(a2), "r"(a3), "r"(b0), "r"(b1));
        }
    }

    int r0g = row0 + w * 16 + gid;
#pragma unroll
    for (int nt = 0; nt < 16; nt++) {
        int c = nt * 8 + tig * 2;
        float bc0 = __ldg(bias + c), bc1 = __ldg(bias + c + 1);
        if (r0g < M) {
            g_h[(size_t)r0g * HID + c]     = fmaxf(acc[nt][0] + bc0, 0.f);
            g_h[(size_t)r0g * HID + c + 1] = fmaxf(acc[nt][1] + bc1, 0.f);
        }
        if (r0g + 8 < M) {
            g_h[(size_t)(r0g + 8) * HID + c]     = fmaxf(acc[nt][2] + bc0, 0.f);
            g_h[(size_t)(r0g + 8) * HID + c + 1] = fmaxf(acc[nt][3] + bc1, 0.f);
        }
    }
}

__device__ __forceinline__ float wredsum(float v) {
#pragma unroll
    for (int o = 16; o; o >>= 1) v += __shfl_xor_sync(0xffffffffu, v, o);
    return v;
}

__device__ __forceinline__ float4 layernorm4(float4 v, float4 lw, float4 lb) {
    float s = wredsum(v.x + v.y + v.z + v.w);
    float m = s * (1.f / 128.f);
    float dx = v.x - m, dy = v.y - m, dz = v.z - m, dw = v.w - m;
    float var = wredsum(dx * dx + dy * dy + dz * dz + dw * dw) * (1.f / 128.f);
    float r = rsqrtf(var + 1e-5f);
    return make_float4(dx * r * lw.x + lb.x, dy * r * lw.y + lb.y,
                       dz * r * lw.z + lb.z, dw * r * lw.w + lb.w);
}

// One warp per node: gather AI over CSR, SIR dynamics, 3x LayerNorm, tail copy.
__global__ void k_fused(const float* __restrict__ x, const float* __restrict__ lnw,
                        const float* __restrict__ lnb, float* __restrict__ out, int n) {
    int warp = threadIdx.x >> 5, lane = threadIdx.x & 31;
    int i = blockIdx.x * 8 + warp;
    if (i >= n) return;

    const float4* h4 = (const float4*)g_h;
    const float4* x4 = (const float4*)x;
    float4* o4 = (float4*)out;

    float4 S = h4[(size_t)i * 32 + lane];
    float4 I = h4[((size_t)n + i) * 32 + lane];
    float4 X = x4[((size_t)3 * n + i) * 32 + lane];
    float beta = __shfl_sync(0xffffffffu, X.x, 0);
    float gam  = __shfl_sync(0xffffffffu, X.y, 0);

    int deg = min(g_cnt[i], CAP);
    float4 AI = make_float4(0.f, 0.f, 0.f, 0.f);
    for (int d0 = 0; d0 < deg; d0 += 32) {
        int m = min(32, deg - d0);
        int c = 0;
        if (lane < m) c = g_csr[(size_t)i * CAP + d0 + lane];
        for (int j = 0; j < m; j++) {
            int cj = __shfl_sync(0xffffffffu, c, j);
            float4 iv = h4[((size_t)n + cj) * 32 + lane];
            AI.x += iv.x; AI.y += iv.y; AI.z += iv.z; AI.w += iv.w;
        }
    }

    float4 dS = make_float4(-beta * AI.x * S.x, -beta * AI.y * S.y,
                            -beta * AI.z * S.z, -beta * AI.w * S.w);
    float4 dI = make_float4(-dS.x - gam * I.x, -dS.y - gam * I.y,
                            -dS.z - gam * I.z, -dS.w - gam * I.w);
    float4 dR = make_float4(gam * I.x, gam * I.y, gam * I.z, gam * I.w);

    float4 lw = __ldg((const float4*)lnw + lane);
    float4 lb = __ldg((const float4*)lnb + lane);

    o4[(size_t)i * 32 + lane]               = layernorm4(dS, lw, lb);
    o4[((size_t)n + i) * 32 + lane]         = layernorm4(dI, lw, lb);
    o4[((size_t)2 * n + i) * 32 + lane]     = layernorm4(dR, lw, lb);
    o4[((size_t)3 * n + i) * 32 + lane]     = X;
}

extern "C" void kernel_launch(void* const* d_in, const int* in_sizes, int n_in,
                              void* d_out, int out_size) {
    // inputs: t, x, edge_row, edge_col, W, b, ln_w, ln_b (t unused)
    const float* x   = (const float*)d_in[1];
    const int*   er  = (const int*)d_in[2];
    const int*   ec  = (const int*)d_in[3];
    const float* W   = (const float*)d_in[4];
    const float* b   = (const float*)d_in[5];
    const float* lnw = (const float*)d_in[6];
    const float* lnb = (const float*)d_in[7];
    float* out = (float*)d_out;

    int n = (in_sizes[1] / HID) / 4;
    int E = in_sizes[2];
    int M = 2 * n;  // only S and I rows of h are ever used

    k_zero<<<(n + 255) / 256, 256>>>(n);
    k_fill<<<(E + 255) / 256, 256>>>(er, ec, E, n);

    const int SMEM = 2 * 128 * 132 * 4;
    cudaFuncSetAttribute(k_gemm, cudaFuncAttributeMaxDynamicSharedMemorySize, SMEM);
    k_gemm<<<(M + 127) / 128, 256, SMEM>>>(x, W, b, M);

    k_fused<<<(n + 7) / 8, 256>>>(x, lnw, lnb, out, n);
}

// round 5
// speedup vs baseline: 1.5130x; 1.5130x over previous
#include <cuda_runtime.h>
#include <cstdint>

#define HID 128
#define NMAX 100000
#define CAP 32
#define WS_STRIDE 144   // 144 mod 32 == 16 -> conflict-free LDS.128 phases

// scratch (no cudaMalloc allowed): h for S,I rows (2n x 128), CSR adjacency
static __device__ float g_h[(size_t)2 * NMAX * HID];     // 102.4 MB
static __device__ int   g_cnt[NMAX];
static __device__ int   g_csr[(size_t)NMAX * CAP];       // 12.8 MB

__global__ void k_zero(int n) {
    int i = blockIdx.x * blockDim.x + threadIdx.x;
    if (i < n) g_cnt[i] = 0;
}

__global__ void k_fill(const int* __restrict__ er,
                       const int* __restrict__ ec, int E, int n) {
    int e = blockIdx.x * blockDim.x + threadIdx.x;
    if (e < E) {
        int r = er[e];
        int c = ec[e];
        if ((unsigned)r < (unsigned)n && (unsigned)c < (unsigned)n) {
            int pos = atomicAdd(&g_cnt[r], 1) & (CAP - 1);
            g_csr[(size_t)r * CAP + pos] = c;
        }
    }
}

__device__ __forceinline__ float to_tf32(float x) {
    unsigned u;
    asm("cvt.rna.tf32.f32 %0, %1;" : "=r"(u) : "f"(x));
    return __uint_as_float(u);
}

__device__ __forceinline__ void mma_tf32(float* acc, unsigned a0, unsigned a1,
                                         unsigned a2, unsigned a3,
                                         unsigned b0, unsigned b1) {
    asm volatile(
        "mma.sync.aligned.m16n8k8.row.col.f32.tf32.tf32.f32 "
        "{%0,%1,%2,%3}, {%4,%5,%6,%7}, {%8,%9}, {%0,%1,%2,%3};"
        : "+f"(acc[0]), "+f"(acc[1]), "+f"(acc[2]), "+f"(acc[3])
        : "r"(a0), "r"(a1), "r"(a2), "r"(a3), "r"(b0), "r"(b1));
}

// H[r][c] = relu(sum_k A[r][k] * W[c][k] + b[c]).
// CTA 256 threads = 8 warps; CTA tile 64 rows x 128 cols.
// Warp w: rows [(w>>1)*16, +16), col half (w&1)*64. A frags direct from gmem
// (LDG.128, k-permuted so thread tig covers src k = k0+4*tig..+3; B smem reads
// use the identical permutation, so the dot product is unchanged).
__global__ __launch_bounds__(256) void k_gemm(const float* __restrict__ A,
                                              const float* __restrict__ W,
                                              const float* __restrict__ bias, int M) {
    extern __shared__ float Ws[];   // 128 x WS_STRIDE tf32, 73.7 KB
    int tid = threadIdx.x;

    for (int i = tid; i < 128 * 32; i += 256) {
        int r = i >> 5, q = i & 31;
        float4 v = *(const float4*)(W + r * HID + q * 4);
        *(float4*)(Ws + r * WS_STRIDE + q * 4) =
            make_float4(to_tf32(v.x), to_tf32(v.y), to_tf32(v.z), to_tf32(v.w));
    }
    __syncthreads();

    int w = tid >> 5, lane = tid & 31;
    int gid = lane >> 2, tig = lane & 3;
    int rw = w >> 1;            // row-warp 0..3
    int ch = w & 1;             // col half 0..1
    int row = blockIdx.x * 64 + rw * 16 + gid;

    const float4* Alo = (const float4*)(A + (size_t)row * HID);        // + chunk*4 + tig
    const float4* Ahi = (const float4*)(A + (size_t)(row + 8) * HID);
    const float* Wb = Ws + (ch * 64) * WS_STRIDE;

    float acc[8][4];
#pragma unroll
    for (int nt = 0; nt < 8; nt++)
        acc[nt][0] = acc[nt][1] = acc[nt][2] = acc[nt][3] = 0.f;

    // NOTE: rows beyond M read into I/R region of x — finite garbage, never stored.
    float4 lo = Alo[tig], hi = Ahi[tig];
#pragma unroll
    for (int c8 = 0; c8 < 8; c8++) {
        float4 nlo, nhi;
        if (c8 < 7) { nlo = Alo[(c8 + 1) * 4 + tig]; nhi = Ahi[(c8 + 1) * 4 + tig]; }
        unsigned lx = __float_as_uint(to_tf32(lo.x)), ly = __float_as_uint(to_tf32(lo.y));
        unsigned lz = __float_as_uint(to_tf32(lo.z)), lw = __float_as_uint(to_tf32(lo.w));
        unsigned hx = __float_as_uint(to_tf32(hi.x)), hy = __float_as_uint(to_tf32(hi.y));
        unsigned hz = __float_as_uint(to_tf32(hi.z)), hw = __float_as_uint(to_tf32(hi.w));
#pragma unroll
        for (int nt = 0; nt < 8; nt++) {
            float4 w4 = *(const float4*)(Wb + (nt * 8 + gid) * WS_STRIDE + c8 * 16 + 4 * tig);
            unsigned wx = __float_as_uint(w4.x), wy = __float_as_uint(w4.y);
            unsigned wz = __float_as_uint(w4.z), ww = __float_as_uint(w4.w);
            mma_tf32(acc[nt], lx, hx, ly, hy, wx, wy);   // src k = k0+4t, k0+4t+1
            mma_tf32(acc[nt], lz, hz, lw, hw, wz, ww);   // src k = k0+4t+2, k0+4t+3
        }
        lo = nlo; hi = nhi;
    }

#pragma unroll
    for (int nt = 0; nt < 8; nt++) {
        int c = ch * 64 + nt * 8 + tig * 2;
        float bc0 = __ldg(bias + c), bc1 = __ldg(bias + c + 1);
        if (row < M) {
            g_h[(size_t)row * HID + c]     = fmaxf(acc[nt][0] + bc0, 0.f);
            g_h[(size_t)row * HID + c + 1] = fmaxf(acc[nt][1] + bc1, 0.f);
        }
        if (row + 8 < M) {
            g_h[(size_t)(row + 8) * HID + c]     = fmaxf(acc[nt][2] + bc0, 0.f);
            g_h[(size_t)(row + 8) * HID + c + 1] = fmaxf(acc[nt][3] + bc1, 0.f);
        }
    }
}

__device__ __forceinline__ float wredsum(float v) {
#pragma unroll
    for (int o = 16; o; o >>= 1) v += __shfl_xor_sync(0xffffffffu, v, o);
    return v;
}

__device__ __forceinline__ float4 layernorm4(float4 v, float4 lw, float4 lb) {
    float s = wredsum(v.x + v.y + v.z + v.w);
    float m = s * (1.f / 128.f);
    float dx = v.x - m, dy = v.y - m, dz = v.z - m, dw = v.w - m;
    float var = wredsum(dx * dx + dy * dy + dz * dz + dw * dw) * (1.f / 128.f);
    float r = rsqrtf(var + 1e-5f);
    return make_float4(dx * r * lw.x + lb.x, dy * r * lw.y + lb.y,
                       dz * r * lw.z + lb.z, dw * r * lw.w + lb.w);
}

// One warp per node: gather AI over CSR, SIR dynamics, 3x LayerNorm, tail copy.
__global__ void k_fused(const float* __restrict__ x, const float* __restrict__ lnw,
                        const float* __restrict__ lnb, float* __restrict__ out, int n) {
    int warp = threadIdx.x >> 5, lane = threadIdx.x & 31;
    int i = blockIdx.x * 8 + warp;
    if (i >= n) return;

    const float4* h4 = (const float4*)g_h;
    const float4* x4 = (const float4*)x;
    float4* o4 = (float4*)out;

    float4 S = h4[(size_t)i * 32 + lane];
    float4 I = h4[((size_t)n + i) * 32 + lane];
    float4 X = x4[((size_t)3 * n + i) * 32 + lane];
    float beta = __shfl_sync(0xffffffffu, X.x, 0);
    float gam  = __shfl_sync(0xffffffffu, X.y, 0);

    int deg = min(g_cnt[i], CAP);
    int c = (lane < deg) ? g_csr[(size_t)i * CAP + lane] : 0;

    float4 A0 = make_float4(0.f, 0.f, 0.f, 0.f);
    float4 A1 = make_float4(0.f, 0.f, 0.f, 0.f);
    int j = 0;
    for (; j + 2 <= deg; j += 2) {
        int c0 = __shfl_sync(0xffffffffu, c, j);
        int c1 = __shfl_sync(0xffffffffu, c, j + 1);
        float4 v0 = h4[((size_t)n + c0) * 32 + lane];
        float4 v1 = h4[((size_t)n + c1) * 32 + lane];
        A0.x += v0.x; A0.y += v0.y; A0.z += v0.z; A0.w += v0.w;
        A1.x += v1.x; A1.y += v1.y; A1.z += v1.z; A1.w += v1.w;
    }
    if (j < deg) {
        int c0 = __shfl_sync(0xffffffffu, c, j);
        float4 v0 = h4[((size_t)n + c0) * 32 + lane];
        A0.x += v0.x; A0.y += v0.y; A0.z += v0.z; A0.w += v0.w;
    }
    float4 AI = make_float4(A0.x + A1.x, A0.y + A1.y, A0.z + A1.z, A0.w + A1.w);

    float4 dS = make_float4(-beta * AI.x * S.x, -beta * AI.y * S.y,
                            -beta * AI.z * S.z, -beta * AI.w * S.w);
    float4 dI = make_float4(-dS.x - gam * I.x, -dS.y - gam * I.y,
                            -dS.z - gam * I.z, -dS.w - gam * I.w);
    float4 dR = make_float4(gam * I.x, gam * I.y, gam * I.z, gam * I.w);

    float4 lw = __ldg((const float4*)lnw + lane);
    float4 lb = __ldg((const float4*)lnb + lane);

    __stcs(&o4[(size_t)i * 32 + lane],           layernorm4(dS, lw, lb));
    __stcs(&o4[((size_t)n + i) * 32 + lane],     layernorm4(dI, lw, lb));
    __stcs(&o4[((size_t)2 * n + i) * 32 + lane], layernorm4(dR, lw, lb));
    __stcs(&o4[((size_t)3 * n + i) * 32 + lane], X);
}

extern "C" void kernel_launch(void* const* d_in, const int* in_sizes, int n_in,
                              void* d_out, int out_size) {
    // inputs: t, x, edge_row, edge_col, W, b, ln_w, ln_b (t unused)
    const float* x   = (const float*)d_in[1];
    const int*   er  = (const int*)d_in[2];
    const int*   ec  = (const int*)d_in[3];
    const float* W   = (const float*)d_in[4];
    const float* b   = (const float*)d_in[5];
    const float* lnw = (const float*)d_in[6];
    const float* lnb = (const float*)d_in[7];
    float* out = (float*)d_out;

    int n = (in_sizes[1] / HID) / 4;
    int E = in_sizes[2];
    int M = 2 * n;  // only S and I rows of h are ever used

    k_zero<<<(n + 255) / 256, 256>>>(n);
    k_fill<<<(E + 255) / 256, 256>>>(er, ec, E, n);

    const int SMEM = 128 * WS_STRIDE * 4;
    cudaFuncSetAttribute(k_gemm, cudaFuncAttributeMaxDynamicSharedMemorySize, SMEM);
    k_gemm<<<(M + 63) / 64, 256, SMEM>>>(x, W, b, M);

    k_fused<<<(n + 7) / 8, 256>>>(x, lnw, lnb, out, n);
}

// round 7
// speedup vs baseline: 1.7712x; 1.1707x over previous
#include <cuda_runtime.h>
#include <cstdint>

#define HID 128
#define NMAX 100000
#define CAP 32
#define WS_STRIDE 144   // 144 mod 32 == 16 -> conflict-free LDS.128 phases
#define GEMM_CTAS 444   // 3 CTAs/SM x 148 SMs, persistent

// scratch (no cudaMalloc allowed). g_cnt is zero at module load; k_fused
// re-zeroes it every run so each execution starts from zeroed counters.
static __device__ float g_h[(size_t)2 * NMAX * HID];     // 102.4 MB
static __device__ int   g_cnt[NMAX];
static __device__ int   g_csr[(size_t)NMAX * CAP];       // 12.8 MB

__device__ __forceinline__ float to_tf32(float x) {
    unsigned u;
    asm("cvt.rna.tf32.f32 %0, %1;" : "=r"(u) : "f"(x));
    return __uint_as_float(u);
}

__device__ __forceinline__ void mma_tf32(float* acc, unsigned a0, unsigned a1,
                                         unsigned a2, unsigned a3,
                                         unsigned b0, unsigned b1) {
    asm volatile(
        "mma.sync.aligned.m16n8k8.row.col.f32.tf32.tf32.f32 "
        "{%0,%1,%2,%3}, {%4,%5,%6,%7}, {%8,%9}, {%0,%1,%2,%3};"
        : "+f"(acc[0]), "+f"(acc[1]), "+f"(acc[2]), "+f"(acc[3])
        : "r"(a0), "r"(a1), "r"(a2), "r"(a3), "r"(b0), "r"(b1));
}

// Persistent GEMM + edge fill.
// h[r][c] = relu(sum_k A[r][k]*W[c][k] + b[c]) for r < M, written to g_h.
// Each CTA: (1) scatters its slice of edges into the CSR, (2) stages W into
// smem once, (3) loops over 64-row tiles with A fragments loaded directly
// from gmem (k-permuted: thread tig covers src k = k0+4*tig..+3; the same
// permutation is applied to the B smem reads, so the contraction matches).
__global__ __launch_bounds__(256, 3) void k_gemm_fill(
    const float* __restrict__ A, const float* __restrict__ W,
    const float* __restrict__ bias, int M,
    const int* __restrict__ er, const int* __restrict__ ec, int E, int n) {
    extern __shared__ float Ws[];   // 128 x WS_STRIDE tf32, 73.7 KB
    int tid = threadIdx.x;

    // --- edge fill slice (independent of GEMM; consumed by k_fused later) ---
    for (int e = blockIdx.x * 256 + tid; e < E; e += GEMM_CTAS * 256) {
        int r = er[e];
        int c = ec[e];
        if ((unsigned)r < (unsigned)n && (unsigned)c < (unsigned)n) {
            int pos = atomicAdd(&g_cnt[r], 1) & (CAP - 1);
            g_csr[(size_t)r * CAP + pos] = c;
        }
    }

    // --- stage W once ---
    for (int i = tid; i < 128 * 32; i += 256) {
        int r = i >> 5, q = i & 31;
        float4 v = *(const float4*)(W + r * HID + q * 4);
        *(float4*)(Ws + r * WS_STRIDE + q * 4) =
            make_float4(to_tf32(v.x), to_tf32(v.y), to_tf32(v.z), to_tf32(v.w));
    }
    __syncthreads();

    int w = tid >> 5, lane = tid & 31;
    int gid = lane >> 2, tig = lane & 3;
    int rw = w >> 1;            // row-warp 0..3
    int ch = w & 1;             // col half 0..1
    const float* Wb = Ws + (ch * 64) * WS_STRIDE;

    int ntiles = (M + 63) >> 6;
    for (int t = blockIdx.x; t < ntiles; t += GEMM_CTAS) {
        int row = t * 64 + rw * 16 + gid;
        const float4* Alo = (const float4*)(A + (size_t)row * HID);
        const float4* Ahi = (const float4*)(A + (size_t)(row + 8) * HID);

        float acc[8][4];
#pragma unroll
        for (int nt = 0; nt < 8; nt++)
            acc[nt][0] = acc[nt][1] = acc[nt][2] = acc[nt][3] = 0.f;

        // rows beyond M read into I/R region of x — finite garbage, never stored
        float4 lo = Alo[tig], hi = Ahi[tig];
#pragma unroll
        for (int c8 = 0; c8 < 8; c8++) {
            float4 nlo, nhi;
            if (c8 < 7) { nlo = Alo[(c8 + 1) * 4 + tig]; nhi = Ahi[(c8 + 1) * 4 + tig]; }
            unsigned lx = __float_as_uint(to_tf32(lo.x)), ly = __float_as_uint(to_tf32(lo.y));
            unsigned lz = __float_as_uint(to_tf32(lo.z)), lw = __float_as_uint(to_tf32(lo.w));
            unsigned hx = __float_as_uint(to_tf32(hi.x)), hy = __float_as_uint(to_tf32(hi.y));
            unsigned hz = __float_as_uint(to_tf32(hi.z)), hw = __float_as_uint(to_tf32(hi.w));
#pragma unroll
            for (int nt = 0; nt < 8; nt++) {
                float4 w4 = *(const float4*)(Wb + (nt * 8 + gid) * WS_STRIDE + c8 * 16 + 4 * tig);
                unsigned wx = __float_as_uint(w4.x), wy = __float_as_uint(w4.y);
                unsigned wz = __float_as_uint(w4.z), ww = __float_as_uint(w4.w);
                mma_tf32(acc[nt], lx, hx, ly, hy, wx, wy);   // src k = k0+4t, +1
                mma_tf32(acc[nt], lz, hz, lw, hw, wz, ww);   // src k = k0+4t+2, +3
            }
            lo = nlo; hi = nhi;
        }

#pragma unroll
        for (int nt = 0; nt < 8; nt++) {
            int c = ch * 64 + nt * 8 + tig * 2;
            float bc0 = __ldg(bias + c), bc1 = __ldg(bias + c + 1);
            if (row < M) {
                g_h[(size_t)row * HID + c]     = fmaxf(acc[nt][0] + bc0, 0.f);
                g_h[(size_t)row * HID + c + 1] = fmaxf(acc[nt][1] + bc1, 0.f);
            }
            if (row + 8 < M) {
                g_h[(size_t)(row + 8) * HID + c]     = fmaxf(acc[nt][2] + bc0, 0.f);
                g_h[(size_t)(row + 8) * HID + c + 1] = fmaxf(acc[nt][3] + bc1, 0.f);
            }
        }
    }
}

__device__ __forceinline__ float wredsum(float v) {
#pragma unroll
    for (int o = 16; o; o >>= 1) v += __shfl_xor_sync(0xffffffffu, v, o);
    return v;
}

__device__ __forceinline__ float4 layernorm4(float4 v, float4 lw, float4 lb) {
    float s = wredsum(v.x + v.y + v.z + v.w);
    float m = s * (1.f / 128.f);
    float dx = v.x - m, dy = v.y - m, dz = v.z - m, dw = v.w - m;
    float var = wredsum(dx * dx + dy * dy + dz * dz + dw * dw) * (1.f / 128.f);
    float r = rsqrtf(var + 1e-5f);
    return make_float4(dx * r * lw.x + lb.x, dy * r * lw.y + lb.y,
                       dz * r * lw.z + lb.z, dw * r * lw.w + lb.w);
}

// One warp per node: gather AI over CSR (MLP-4), SIR dynamics, 3x LN, tail copy.
// Also resets g_cnt[i] to 0 so the next execution starts from zeroed counters.
__global__ __launch_bounds__(256) void k_fused(
    const float* __restrict__ x, const float* __restrict__ lnw,
    const float* __restrict__ lnb, float* __restrict__ out, int n) {
    int warp = threadIdx.x >> 5, lane = threadIdx.x & 31;
    int i = blockIdx.x * 8 + warp;
    if (i >= n) return;

    const float4* h4 = (const float4*)g_h;
    const float4* x4 = (const float4*)x;
    float4* o4 = (float4*)out;

    float4 S = h4[(size_t)i * 32 + lane];
    float4 I = h4[((size_t)n + i) * 32 + lane];
    float4 X = x4[((size_t)3 * n + i) * 32 + lane];
    float beta = __shfl_sync(0xffffffffu, X.x, 0);
    float gam  = __shfl_sync(0xffffffffu, X.y, 0);

    int deg = min(g_cnt[i], CAP);
    if (lane == 0) g_cnt[i] = 0;                 // restore invariant for next run
    int c = (lane < deg) ? g_csr[(size_t)i * CAP + lane] : 0;

    float4 A0 = make_float4(0.f, 0.f, 0.f, 0.f);
    float4 A1 = make_float4(0.f, 0.f, 0.f, 0.f);
    float4 A2 = make_float4(0.f, 0.f, 0.f, 0.f);
    float4 A3 = make_float4(0.f, 0.f, 0.f, 0.f);
    int j = 0;
    for (; j + 4 <= deg; j += 4) {
        int c0 = __shfl_sync(0xffffffffu, c, j);
        int c1 = __shfl_sync(0xffffffffu, c, j + 1);
        int c2 = __shfl_sync(0xffffffffu, c, j + 2);
        int c3 = __shfl_sync(0xffffffffu, c, j + 3);
        float4 v0 = h4[((size_t)n + c0) * 32 + lane];
        float4 v1 = h4[((size_t)n + c1) * 32 + lane];
        float4 v2 = h4[((size_t)n + c2) * 32 + lane];
        float4 v3 = h4[((size_t)n + c3) * 32 + lane];
        A0.x += v0.x; A0.y += v0.y; A0.z += v0.z; A0.w += v0.w;
        A1.x += v1.x; A1.y += v1.y; A1.z += v1.z; A1.w += v1.w;
        A2.x += v2.x; A2.y += v2.y; A2.z += v2.z; A2.w += v2.w;
        A3.x += v3.x; A3.y += v3.y; A3.z += v3.z; A3.w += v3.w;
    }
    for (; j < deg; j++) {
        int c0 = __shfl_sync(0xffffffffu, c, j);
        float4 v0 = h4[((size_t)n + c0) * 32 + lane];
        A0.x += v0.x; A0.y += v0.y; A0.z += v0.z; A0.w += v0.w;
    }
    float4 AI = make_float4((A0.x + A1.x) + (A2.x + A3.x),
                            (A0.y + A1.y) + (A2.y + A3.y),
                            (A0.z + A1.z) + (A2.z + A3.z),
                            (A0.w + A1.w) + (A2.w + A3.w));

    float4 dS = make_float4(-beta * AI.x * S.x, -beta * AI.y * S.y,
                            -beta * AI.z * S.z, -beta * AI.w * S.w);
    float4 dI = make_float4(-dS.x - gam * I.x, -dS.y - gam * I.y,
                            -dS.z - gam * I.z, -dS.w - gam * I.w);
    float4 dR = make_float4(gam * I.x, gam * I.y, gam * I.z, gam * I.w);

    float4 lw = __ldg((const float4*)lnw + lane);
    float4 lb = __ldg((const float4*)lnb + lane);

    __stcs(&o4[(size_t)i * 32 + lane],           layernorm4(dS, lw, lb));
    __stcs(&o4[((size_t)n + i) * 32 + lane],     layernorm4(dI, lw, lb));
    __stcs(&o4[((size_t)2 * n + i) * 32 + lane], layernorm4(dR, lw, lb));
    __stcs(&o4[((size_t)3 * n + i) * 32 + lane], X);
}

extern "C" void kernel_launch(void* const* d_in, const int* in_sizes, int n_in,
                              void* d_out, int out_size) {
    // inputs: t, x, edge_row, edge_col, W, b, ln_w, ln_b (t unused)
    const float* x   = (const float*)d_in[1];
    const int*   er  = (const int*)d_in[2];
    const int*   ec  = (const int*)d_in[3];
    const float* W   = (const float*)d_in[4];
    const float* b   = (const float*)d_in[5];
    const float* lnw = (const float*)d_in[6];
    const float* lnb = (const float*)d_in[7];
    float* out = (float*)d_out;

    int n = (in_sizes[1] / HID) / 4;
    int E = in_sizes[2];
    int M = 2 * n;  // only S and I rows of h are ever used

    const int SMEM = 128 * WS_STRIDE * 4;
    cudaFuncSetAttribute(k_gemm_fill, cudaFuncAttributeMaxDynamicSharedMemorySize, SMEM);
    k_gemm_fill<<<GEMM_CTAS, 256, SMEM>>>(x, W, b, M, er, ec, E, n);

    k_fused<<<(n + 7) / 8, 256>>>(x, lnw, lnb, out, n);
}

// round 8
// speedup vs baseline: 1.7969x; 1.0145x over previous
#include <cuda_runtime.h>
#include <cstdint>

#define HID 128
#define NMAX 100000
#define CAP 32
#define WS_STRIDE 144   // 144 mod 32 == 16 -> conflict-free LDS.128 phases
#define GEMM_CTAS 444   // 3 CTAs/SM x 148 SMs, persistent

// scratch (no cudaMalloc allowed). g_cnt is zero at module load; k_fused
// re-zeroes it every run so each execution starts from zeroed counters.
static __device__ float g_h[(size_t)2 * NMAX * HID];     // 102.4 MB
static __device__ int   g_cnt[NMAX];
static __device__ int   g_csr[(size_t)NMAX * CAP];       // 12.8 MB

__device__ __forceinline__ float to_tf32(float x) {
    unsigned u;
    asm("cvt.rna.tf32.f32 %0, %1;" : "=r"(u) : "f"(x));
    return __uint_as_float(u);
}

__device__ __forceinline__ void mma_tf32(float* acc, unsigned a0, unsigned a1,
                                         unsigned a2, unsigned a3,
                                         unsigned b0, unsigned b1) {
    asm volatile(
        "mma.sync.aligned.m16n8k8.row.col.f32.tf32.tf32.f32 "
        "{%0,%1,%2,%3}, {%4,%5,%6,%7}, {%8,%9}, {%0,%1,%2,%3};"
        : "+f"(acc[0]), "+f"(acc[1]), "+f"(acc[2]), "+f"(acc[3])
        : "r"(a0), "r"(a1), "r"(a2), "r"(a3), "r"(b0), "r"(b1));
}

// Persistent GEMM + edge fill (unchanged from R6 — near legacy-mma rate ceiling).
__global__ __launch_bounds__(256, 3) void k_gemm_fill(
    const float* __restrict__ A, const float* __restrict__ W,
    const float* __restrict__ bias, int M,
    const int* __restrict__ er, const int* __restrict__ ec, int E, int n) {
    extern __shared__ float Ws[];   // 128 x WS_STRIDE tf32, 73.7 KB
    int tid = threadIdx.x;

    // --- edge fill slice ---
    for (int e = blockIdx.x * 256 + tid; e < E; e += GEMM_CTAS * 256) {
        int r = er[e];
        int c = ec[e];
        if ((unsigned)r < (unsigned)n && (unsigned)c < (unsigned)n) {
            int pos = atomicAdd(&g_cnt[r], 1) & (CAP - 1);
            g_csr[(size_t)r * CAP + pos] = c;
        }
    }

    // --- stage W once ---
    for (int i = tid; i < 128 * 32; i += 256) {
        int r = i >> 5, q = i & 31;
        float4 v = *(const float4*)(W + r * HID + q * 4);
        *(float4*)(Ws + r * WS_STRIDE + q * 4) =
            make_float4(to_tf32(v.x), to_tf32(v.y), to_tf32(v.z), to_tf32(v.w));
    }
    __syncthreads();

    int w = tid >> 5, lane = tid & 31;
    int gid = lane >> 2, tig = lane & 3;
    int rw = w >> 1;            // row-warp 0..3
    int ch = w & 1;             // col half 0..1
    const float* Wb = Ws + (ch * 64) * WS_STRIDE;

    int ntiles = (M + 63) >> 6;
    for (int t = blockIdx.x; t < ntiles; t += GEMM_CTAS) {
        int row = t * 64 + rw * 16 + gid;
        const float4* Alo = (const float4*)(A + (size_t)row * HID);
        const float4* Ahi = (const float4*)(A + (size_t)(row + 8) * HID);

        float acc[8][4];
#pragma unroll
        for (int nt = 0; nt < 8; nt++)
            acc[nt][0] = acc[nt][1] = acc[nt][2] = acc[nt][3] = 0.f;

        // rows beyond M read into I/R region of x — finite garbage, never stored
        float4 lo = Alo[tig], hi = Ahi[tig];
#pragma unroll
        for (int c8 = 0; c8 < 8; c8++) {
            float4 nlo, nhi;
            if (c8 < 7) { nlo = Alo[(c8 + 1) * 4 + tig]; nhi = Ahi[(c8 + 1) * 4 + tig]; }
            unsigned lx = __float_as_uint(to_tf32(lo.x)), ly = __float_as_uint(to_tf32(lo.y));
            unsigned lz = __float_as_uint(to_tf32(lo.z)), lw = __float_as_uint(to_tf32(lo.w));
            unsigned hx = __float_as_uint(to_tf32(hi.x)), hy = __float_as_uint(to_tf32(hi.y));
            unsigned hz = __float_as_uint(to_tf32(hi.z)), hw = __float_as_uint(to_tf32(hi.w));
#pragma unroll
            for (int nt = 0; nt < 8; nt++) {
                float4 w4 = *(const float4*)(Wb + (nt * 8 + gid) * WS_STRIDE + c8 * 16 + 4 * tig);
                unsigned wx = __float_as_uint(w4.x), wy = __float_as_uint(w4.y);
                unsigned wz = __float_as_uint(w4.z), ww = __float_as_uint(w4.w);
                mma_tf32(acc[nt], lx, hx, ly, hy, wx, wy);   // src k = k0+4t, +1
                mma_tf32(acc[nt], lz, hz, lw, hw, wz, ww);   // src k = k0+4t+2, +3
            }
            lo = nlo; hi = nhi;
        }

#pragma unroll
        for (int nt = 0; nt < 8; nt++) {
            int c = ch * 64 + nt * 8 + tig * 2;
            float bc0 = __ldg(bias + c), bc1 = __ldg(bias + c + 1);
            if (row < M) {
                g_h[(size_t)row * HID + c]     = fmaxf(acc[nt][0] + bc0, 0.f);
                g_h[(size_t)row * HID + c + 1] = fmaxf(acc[nt][1] + bc1, 0.f);
            }
            if (row + 8 < M) {
                g_h[(size_t)(row + 8) * HID + c]     = fmaxf(acc[nt][2] + bc0, 0.f);
                g_h[(size_t)(row + 8) * HID + c + 1] = fmaxf(acc[nt][3] + bc1, 0.f);
            }
        }
    }
}

__device__ __forceinline__ float4 ln_apply(float4 v, float m, float rinv,
                                           float4 lw, float4 lb) {
    return make_float4((v.x - m) * rinv * lw.x + lb.x,
                       (v.y - m) * rinv * lw.y + lb.y,
                       (v.z - m) * rinv * lw.z + lb.z,
                       (v.w - m) * rinv * lw.w + lb.w);
}

// One warp per node: gather AI (unroll-2, 48-reg budget), SIR dynamics,
// 3x LayerNorm with ALL SIX moment reductions interleaved in ONE butterfly
// (single-pass var = E[v^2] - m^2), tail copy. Resets g_cnt for next run.
__global__ __launch_bounds__(256) void k_fused(
    const float* __restrict__ x, const float* __restrict__ lnw,
    const float* __restrict__ lnb, float* __restrict__ out, int n) {
    int warp = threadIdx.x >> 5, lane = threadIdx.x & 31;
    int i = blockIdx.x * 8 + warp;
    if (i >= n) return;

    const float4* h4 = (const float4*)g_h;
    const float4* x4 = (const float4*)x;
    float4* o4 = (float4*)out;

    float4 S = __ldcs(&h4[(size_t)i * 32 + lane]);            // read-once: stream
    float4 I = h4[((size_t)n + i) * 32 + lane];               // reused by gathers: cache
    float4 X = __ldcs(&x4[((size_t)3 * n + i) * 32 + lane]);
    float beta = __shfl_sync(0xffffffffu, X.x, 0);
    float gam  = __shfl_sync(0xffffffffu, X.y, 0);

    int deg = min(g_cnt[i], CAP);
    if (lane == 0) g_cnt[i] = 0;                 // restore invariant for next run
    int c = (lane < deg) ? g_csr[(size_t)i * CAP + lane] : 0;

    float4 A0 = make_float4(0.f, 0.f, 0.f, 0.f);
    float4 A1 = make_float4(0.f, 0.f, 0.f, 0.f);
    int j = 0;
    for (; j + 2 <= deg; j += 2) {
        int c0 = __shfl_sync(0xffffffffu, c, j);
        int c1 = __shfl_sync(0xffffffffu, c, j + 1);
        float4 v0 = h4[((size_t)n + c0) * 32 + lane];
        float4 v1 = h4[((size_t)n + c1) * 32 + lane];
        A0.x += v0.x; A0.y += v0.y; A0.z += v0.z; A0.w += v0.w;
        A1.x += v1.x; A1.y += v1.y; A1.z += v1.z; A1.w += v1.w;
    }
    if (j < deg) {
        int c0 = __shfl_sync(0xffffffffu, c, j);
        float4 v0 = h4[((size_t)n + c0) * 32 + lane];
        A0.x += v0.x; A0.y += v0.y; A0.z += v0.z; A0.w += v0.w;
    }
    float4 AI = make_float4(A0.x + A1.x, A0.y + A1.y, A0.z + A1.z, A0.w + A1.w);

    float4 dS = make_float4(-beta * AI.x * S.x, -beta * AI.y * S.y,
                            -beta * AI.z * S.z, -beta * AI.w * S.w);
    float4 dI = make_float4(-dS.x - gam * I.x, -dS.y - gam * I.y,
                            -dS.z - gam * I.z, -dS.w - gam * I.w);
    float4 dR = make_float4(gam * I.x, gam * I.y, gam * I.z, gam * I.w);

    // six interleaved moment reductions: (s1, s2) for dS, dI, dR
    float sa1 = (dS.x + dS.y) + (dS.z + dS.w);
    float sa2 = (dS.x * dS.x + dS.y * dS.y) + (dS.z * dS.z + dS.w * dS.w);
    float sb1 = (dI.x + dI.y) + (dI.z + dI.w);
    float sb2 = (dI.x * dI.x + dI.y * dI.y) + (dI.z * dI.z + dI.w * dI.w);
    float sc1 = (dR.x + dR.y) + (dR.z + dR.w);
    float sc2 = (dR.x * dR.x + dR.y * dR.y) + (dR.z * dR.z + dR.w * dR.w);
#pragma unroll
    for (int o = 16; o; o >>= 1) {
        sa1 += __shfl_xor_sync(0xffffffffu, sa1, o);
        sa2 += __shfl_xor_sync(0xffffffffu, sa2, o);
        sb1 += __shfl_xor_sync(0xffffffffu, sb1, o);
        sb2 += __shfl_xor_sync(0xffffffffu, sb2, o);
        sc1 += __shfl_xor_sync(0xffffffffu, sc1, o);
        sc2 += __shfl_xor_sync(0xffffffffu, sc2, o);
    }
    float ma = sa1 * (1.f / 128.f), mb = sb1 * (1.f / 128.f), mc = sc1 * (1.f / 128.f);
    float ra = rsqrtf(fmaxf(sa2 * (1.f / 128.f) - ma * ma, 0.f) + 1e-5f);
    float rb = rsqrtf(fmaxf(sb2 * (1.f / 128.f) - mb * mb, 0.f) + 1e-5f);
    float rc = rsqrtf(fmaxf(sc2 * (1.f / 128.f) - mc * mc, 0.f) + 1e-5f);

    float4 lw = __ldg((const float4*)lnw + lane);
    float4 lb = __ldg((const float4*)lnb + lane);

    __stcs(&o4[(size_t)i * 32 + lane],           ln_apply(dS, ma, ra, lw, lb));
    __stcs(&o4[((size_t)n + i) * 32 + lane],     ln_apply(dI, mb, rb, lw, lb));
    __stcs(&o4[((size_t)2 * n + i) * 32 + lane], ln_apply(dR, mc, rc, lw, lb));
    __stcs(&o4[((size_t)3 * n + i) * 32 + lane], X);
}

extern "C" void kernel_launch(void* const* d_in, const int* in_sizes, int n_in,
                              void* d_out, int out_size) {
    // inputs: t, x, edge_row, edge_col, W, b, ln_w, ln_b (t unused)
    const float* x   = (const float*)d_in[1];
    const int*   er  = (const int*)d_in[2];
    const int*   ec  = (const int*)d_in[3];
    const float* W   = (const float*)d_in[4];
    const float* b   = (const float*)d_in[5];
    const float* lnw = (const float*)d_in[6];
    const float* lnb = (const float*)d_in[7];
    float* out = (float*)d_out;

    int n = (in_sizes[1] / HID) / 4;
    int E = in_sizes[2];
    int M = 2 * n;  // only S and I rows of h are ever used

    const int SMEM = 128 * WS_STRIDE * 4;
    cudaFuncSetAttribute(k_gemm_fill, cudaFuncAttributeMaxDynamicSharedMemorySize, SMEM);
    k_gemm_fill<<<GEMM_CTAS, 256, SMEM>>>(x, W, b, M, er, ec, E, n);

    k_fused<<<(n + 7) / 8, 256>>>(x, lnw, lnb, out, n);
}